// round 13
// baseline (speedup 1.0000x reference)
#include <cuda_runtime.h>

// ---------------- DCT-II 8-point constants (fp32, match np.float32(D)) ----
#define G_ 0.35355339059327373f
#define A_ 0.49039264020161522f
#define B_ 0.41573480615127262f
#define C_ 0.27778511650980114f
#define D_ 0.09754516100806417f
#define E_ 0.46193976625564337f
#define F_ 0.19134171618254492f

#define MAGIC 12582912.0f   // 1.5 * 2^23, RNE folding constant

// Quant tables for QUALITY=95, NATURAL row-major layout, packed per entry as
// (qLuma, 1/qLuma, qChroma, 1/qChroma). Indexed [l*8+k] = row l, col k.
#define QQ(a,b) {(float)(a), 1.0f/(float)(a), (float)(b), 1.0f/(float)(b)}
__constant__ float4 c_tab4[64] = {
    QQ(2,2),QQ(1,2),QQ(1,2),QQ(2,5),QQ(2,10),QQ(4,10),QQ(5,10),QQ(6,10),
    QQ(1,2),QQ(1,2),QQ(1,3),QQ(2,7),QQ(3,10),QQ(6,10),QQ(6,10),QQ(6,10),
    QQ(1,2),QQ(1,3),QQ(2,6),QQ(2,10),QQ(4,10),QQ(6,10),QQ(7,10),QQ(6,10),
    QQ(1,5),QQ(2,7),QQ(2,10),QQ(3,10),QQ(5,10),QQ(9,10),QQ(8,10),QQ(6,10),
    QQ(2,10),QQ(2,10),QQ(4,10),QQ(6,10),QQ(7,10),QQ(11,10),QQ(10,10),QQ(8,10),
    QQ(2,10),QQ(4,10),QQ(6,10),QQ(6,10),QQ(8,10),QQ(10,10),QQ(11,10),QQ(9,10),
    QQ(5,10),QQ(6,10),QQ(8,10),QQ(9,10),QQ(10,10),QQ(12,10),QQ(12,10),QQ(10,10),
    QQ(7,10),QQ(9,10),QQ(10,10),QQ(10,10),QQ(11,10),QQ(10,10),QQ(10,10),QQ(10,10)
};

#define IMGW 512
#define TW   64       // tile width (pixels)
#define TH   32       // tile height (pixels)
#define SYS  68       // padded stride of Y plane in smem (64 + 4)
#define SCS  36       // padded stride of chroma planes (32 + 4)
#define NTHR 128

// round-to-nearest-even via magic constant (|x| < 2^22 guaranteed here)
__device__ __forceinline__ float rne(float v) {
    float t = fmaf(v, 1.0f, MAGIC);
    return fmaf(t, 1.0f, -MAGIC);
}

__device__ __forceinline__ void fdct8(const float x[8], float o[8]) {
    float s07 = x[0] + x[7], s16 = x[1] + x[6], s25 = x[2] + x[5], s34 = x[3] + x[4];
    float d07 = x[0] - x[7], d16 = x[1] - x[6], d25 = x[2] - x[5], d34 = x[3] - x[4];
    float e0 = s07 + s34, e1 = s16 + s25, e2 = s07 - s34, e3 = s16 - s25;
    o[0] = G_ * (e0 + e1);
    o[4] = G_ * (e0 - e1);
    o[2] = fmaf( F_, e3, E_ * e2);
    o[6] = fmaf(-E_, e3, F_ * e2);
    o[1] = fmaf( D_, d34, fmaf( C_, d25, fmaf( B_, d16, A_ * d07)));
    o[3] = fmaf(-C_, d34, fmaf(-A_, d25, fmaf(-D_, d16, B_ * d07)));
    o[5] = fmaf( B_, d34, fmaf( D_, d25, fmaf(-A_, d16, C_ * d07)));
    o[7] = fmaf(-A_, d34, fmaf( B_, d25, fmaf(-C_, d16, D_ * d07)));
}

__device__ __forceinline__ void idct8(const float x[8], float o[8]) {
    float ee0 = G_ * (x[0] + x[4]);
    float ee1 = G_ * (x[0] - x[4]);
    float eo0 = fmaf( F_, x[6], E_ * x[2]);
    float eo1 = fmaf(-E_, x[6], F_ * x[2]);
    float ev0 = ee0 + eo0, ev1 = ee1 + eo1, ev2 = ee1 - eo1, ev3 = ee0 - eo0;
    float od0 = fmaf( D_, x[7], fmaf( C_, x[5], fmaf( B_, x[3], A_ * x[1])));
    float od1 = fmaf(-C_, x[7], fmaf(-A_, x[5], fmaf(-D_, x[3], B_ * x[1])));
    float od2 = fmaf( B_, x[7], fmaf( D_, x[5], fmaf(-A_, x[3], C_ * x[1])));
    float od3 = fmaf(-A_, x[7], fmaf( B_, x[5], fmaf(-C_, x[3], D_ * x[1])));
    o[0] = ev0 + od0; o[1] = ev1 + od1; o[2] = ev2 + od2; o[3] = ev3 + od3;
    o[4] = ev3 - od3; o[5] = ev2 - od2; o[6] = ev1 - od1; o[7] = ev0 - od0;
}

template <int S>
__device__ __forceinline__ void storerow(float* blk, int k, const float a[8]) {
    *reinterpret_cast<float4*>(blk + k * S)     = make_float4(a[0], a[1], a[2], a[3]);
    *reinterpret_cast<float4*>(blk + k * S + 4) = make_float4(a[4], a[5], a[6], a[7]);
}
template <int S>
__device__ __forceinline__ void loadrow(const float* blk, int k, float a[8]) {
    float4 v0 = *reinterpret_cast<const float4*>(blk + k * S);
    float4 v1 = *reinterpret_cast<const float4*>(blk + k * S + 4);
    a[0] = v0.x; a[1] = v0.y; a[2] = v0.z; a[3] = v0.w;
    a[4] = v1.x; a[5] = v1.y; a[6] = v1.z; a[7] = v1.w;
}
// Store thread's 8-vector as COLUMN k of the block (scalar STS, conflict-free
// given the group-base layouts used below).
template <int S>
__device__ __forceinline__ void storecol(float* blk, int k, const float a[8]) {
#pragma unroll
    for (int j = 0; j < 8; j++) blk[j * S + k] = a[j];
}

// ONE chroma 8x8 block: DCT -> quant -> dequant -> IDCT, written back to smem.
template <int SC>
__device__ __forceinline__ void jpeg_block1(float* b2, int k,
                                            const float4* __restrict__ tab) {
    float x2[8], a2[8];
    loadrow<SC>(b2, k, x2);
    fdct8(x2, a2);
    __syncwarp();
    storecol<SC>(b2, k, a2);
    __syncwarp();
    loadrow<SC>(b2, k, x2);
    fdct8(x2, a2);
#pragma unroll
    for (int l = 0; l < 8; l++) {
        float4 t = tab[l * 8 + k];
        a2[l] = (fmaf(a2[l], t.w, MAGIC) - MAGIC) * t.z;
    }
    idct8(a2, x2);
    storecol<SC>(b2, k, x2);
    __syncwarp();
    loadrow<SC>(b2, k, x2);
    idct8(x2, a2);
    storerow<SC>(b2, k, a2);
}

// TWO luma 8x8 blocks interleaved; ENDS with reconstructed rows in registers
// (r0, r1) instead of writing back to smem.
template <int SL>
__device__ __forceinline__ void jpeg_block2_reg(float* b0, float* b1, int k,
                                                const float4* __restrict__ tab,
                                                float r0[8], float r1[8]) {
    float x0[8], x1[8], a0[8], a1[8];
    loadrow<SL>(b0, k, x0);
    loadrow<SL>(b1, k, x1);
    fdct8(x0, a0);
    fdct8(x1, a1);
    __syncwarp();
    storecol<SL>(b0, k, a0);
    storecol<SL>(b1, k, a1);
    __syncwarp();
    loadrow<SL>(b0, k, x0);
    loadrow<SL>(b1, k, x1);
    fdct8(x0, a0);
    fdct8(x1, a1);
#pragma unroll
    for (int l = 0; l < 8; l++) {
        float4 t = tab[l * 8 + k];
        a0[l] = (fmaf(a0[l], t.y, MAGIC) - MAGIC) * t.x;
        a1[l] = (fmaf(a1[l], t.y, MAGIC) - MAGIC) * t.x;
    }
    idct8(a0, x0);
    idct8(a1, x1);
    storecol<SL>(b0, k, x0);
    storecol<SL>(b1, k, x1);
    __syncwarp();
    loadrow<SL>(b0, k, x0);
    loadrow<SL>(b1, k, x1);
    idct8(x0, r0);      // reconstructed row k of block 0, stays in registers
    idct8(x1, r1);
}

// Emit one reconstructed luma row (8 px, centered) as RGB floats to gmem.
// Chroma (centered) read as one float4 per plane (broadcast pairs, no conflict).
__device__ __forceinline__ void emit_row(float* __restrict__ dst, int tilerow,
                                         int bcol, const float y[8],
                                         const float* __restrict__ sCb,
                                         const float* __restrict__ sCr) {
    int crow = tilerow >> 1;
    float4 cbq = *reinterpret_cast<const float4*>(&sCb[crow * SCS + bcol * 4]);
    float4 crq = *reinterpret_cast<const float4*>(&sCr[crow * SCS + bcol * 4]);
    float cbv[4] = { cbq.x, cbq.y, cbq.z, cbq.w };
    float crv[4] = { crq.x, crq.y, crq.z, crq.w };
    float o[24];
#pragma unroll
    for (int i = 0; i < 8; i++) {
        float cb = cbv[i >> 1], cr = crv[i >> 1];
        float y128 = y[i] + 128.0f;
        float r2 = fmaf(cr, 1.402f, y128);
        float g2 = fmaf(cb, -0.344136f, fmaf(cr, -0.714136f, y128));
        float b2 = fmaf(cb, 1.772f, y128);
        // round(clip(v,0,255))/255 == sat(rne(v)/255): clamp folds into FMUL.SAT
        o[i*3+0] = __saturatef(rne(r2) * (1.0f / 255.0f));
        o[i*3+1] = __saturatef(rne(g2) * (1.0f / 255.0f));
        o[i*3+2] = __saturatef(rne(b2) * (1.0f / 255.0f));
    }
    float* pr = dst + tilerow * (IMGW * 3) + bcol * 24;   // 96B-aligned
#pragma unroll
    for (int q = 0; q < 6; q++)
        *reinterpret_cast<float4*>(pr + q * 4) =
            make_float4(o[q*4+0], o[q*4+1], o[q*4+2], o[q*4+3]);
}

__global__ void __launch_bounds__(NTHR, 7)
jpeg_kernel(const float* __restrict__ in, float* __restrict__ out) {
    __shared__ float sY[TH * SYS];           // 32 x 68
    __shared__ float sCb[16 * SCS];          // 16 x 36 (chroma 32x16)
    __shared__ float sCr[16 * SCS];
    __shared__ __align__(16) float4 sTab[64];

    const int tid = threadIdx.x;
    const int tx0 = blockIdx.x * TW;
    const int ty0 = blockIdx.y * TH;
    const int img = blockIdx.z;

    if (tid < 64) sTab[tid] = c_tab4[tid];   // covered by phase-1 barrier

    const float* src = in  + (((size_t)img * IMGW + ty0) * IMGW + tx0) * 3;
    float*       dst = out + (((size_t)img * IMGW + ty0) * IMGW + tx0) * 3;

    // ---------- phase 1: LDG.128, x255, RGB->YCbCr, 4:2:0 downsample ----------
    // Region = 4px wide x 2 rows. Chroma from RGB sums of each 2x2 quad
    // (transform linear; /4 folded into coefficients).
#pragma unroll
    for (int it = 0; it < 2; it++) {
        int sid = tid + it * NTHR;
        int col = sid & 15, rp = sid >> 4;
        const float* p = src + (rp * 2) * (IMGW * 3) + col * 12;
        float rs[2] = {0.0f, 0.0f}, gs[2] = {0.0f, 0.0f}, bs[2] = {0.0f, 0.0f};
#pragma unroll
        for (int dy = 0; dy < 2; dy++) {
            const float* pr = p + dy * (IMGW * 3);
            float4 q0 = *reinterpret_cast<const float4*>(pr);
            float4 q1 = *reinterpret_cast<const float4*>(pr + 4);
            float4 q2 = *reinterpret_cast<const float4*>(pr + 8);
            float rv[4] = { q0.x, q0.w, q1.z, q2.y };
            float gv[4] = { q0.y, q1.x, q1.w, q2.z };
            float bv[4] = { q0.z, q1.y, q2.x, q2.w };
            float y4[4];
#pragma unroll
            for (int i = 0; i < 4; i++) {
                // input uniform [0,1): floor(x*255) in [0,254], no clip needed
                float r = floorf(rv[i] * 255.0f);
                float g = floorf(gv[i] * 255.0f);
                float b = floorf(bv[i] * 255.0f);
                y4[i] = fmaf(r, 0.299f, fmaf(g, 0.587f, fmaf(b, 0.114f, -128.0f)));
                rs[i >> 1] += r; gs[i >> 1] += g; bs[i >> 1] += b;
            }
            *reinterpret_cast<float4*>(&sY[(rp * 2 + dy) * SYS + col * 4]) =
                make_float4(y4[0], y4[1], y4[2], y4[3]);
        }
        float cb0 = fmaf(rs[0], -0.042184f, fmaf(gs[0], -0.082816f, bs[0] * 0.125f));
        float cb1 = fmaf(rs[1], -0.042184f, fmaf(gs[1], -0.082816f, bs[1] * 0.125f));
        float cr0 = fmaf(rs[0], 0.125f, fmaf(gs[0], -0.104672f, bs[0] * (-0.020328f)));
        float cr1 = fmaf(rs[1], 0.125f, fmaf(gs[1], -0.104672f, bs[1] * (-0.020328f)));
        *reinterpret_cast<float2*>(&sCb[rp * SCS + col * 2]) = make_float2(cb0, cb1);
        *reinterpret_cast<float2*>(&sCr[rp * SCS + col * 2]) = make_float2(cr0, cr1);
    }
    __syncthreads();

    const int grp = tid >> 3;   // 0..15
    const int k   = tid & 7;
    const float4* tab = sTab;

    // ---------- phase 2a: 16 chroma blocks, one per group --------------------
    {
        // 4 block-cols x 2 block-rows per plane; grp<8 -> Cb, else Cr
        int cg = grp & 7;
        float* cbase = (grp < 8) ? sCb : sCr;
        float* cb = cbase + (cg >> 2) * (8 * SCS) + (cg & 3) * 8;
        jpeg_block1<SCS>(cb, k, tab);
    }
    __syncthreads();   // all reconstructed chroma visible before luma emit

    // ---------- phase 2b: 32 luma blocks as 16 interleaved pairs; output ------
    // fused: final IDCT rows stay in registers -> RGB -> STG (no phase 3).
    {
        const int brow0 = grp >> 3;          // 0 or 1
        const int bcol  = grp & 7;
        float* yb0 = sY + brow0 * (8 * SYS) + bcol * 8;
        float* yb1 = sY + (brow0 + 2) * (8 * SYS) + bcol * 8;

        float r0[8], r1[8];
        jpeg_block2_reg<SYS>(yb0, yb1, k, tab, r0, r1);

        emit_row(dst, brow0 * 8 + k, bcol, r0, sCb, sCr);
        emit_row(dst, (brow0 + 2) * 8 + k, bcol, r1, sCb, sCr);
    }
}

extern "C" void kernel_launch(void* const* d_in, const int* in_sizes, int n_in,
                              void* d_out, int out_size) {
    (void)in_sizes; (void)n_in; (void)out_size;
    dim3 grid(IMGW / TW, IMGW / TH, 32);
    jpeg_kernel<<<grid, NTHR>>>((const float*)d_in[0], (float*)d_out);
}

// round 14
// speedup vs baseline: 1.0980x; 1.0980x over previous
#include <cuda_runtime.h>

// ---------------- DCT-II 8-point constants (fp32, match np.float32(D)) ----
#define G_ 0.35355339059327373f
#define A_ 0.49039264020161522f
#define B_ 0.41573480615127262f
#define C_ 0.27778511650980114f
#define D_ 0.09754516100806417f
#define E_ 0.46193976625564337f
#define F_ 0.19134171618254492f

// Quant tables for QUALITY=95 in NATURAL layout, packed (q, 1/q).
#define QP(v) {(float)(v), 1.0f/(float)(v)}
__constant__ float2 c_tab2[128] = {
    // luma (natural row-major)
    QP(2),QP(1),QP(1),QP(2),QP(2),QP(4),QP(5),QP(6),
    QP(1),QP(1),QP(1),QP(2),QP(3),QP(6),QP(6),QP(6),
    QP(1),QP(1),QP(2),QP(2),QP(4),QP(6),QP(7),QP(6),
    QP(1),QP(2),QP(2),QP(3),QP(5),QP(9),QP(8),QP(6),
    QP(2),QP(2),QP(4),QP(6),QP(7),QP(11),QP(10),QP(8),
    QP(2),QP(4),QP(6),QP(6),QP(8),QP(10),QP(11),QP(9),
    QP(5),QP(6),QP(8),QP(9),QP(10),QP(12),QP(12),QP(10),
    QP(7),QP(9),QP(10),QP(10),QP(11),QP(10),QP(10),QP(10),
    // chroma (natural row-major, symmetric)
    QP(2),QP(2),QP(2),QP(5),QP(10),QP(10),QP(10),QP(10),
    QP(2),QP(2),QP(3),QP(7),QP(10),QP(10),QP(10),QP(10),
    QP(2),QP(3),QP(6),QP(10),QP(10),QP(10),QP(10),QP(10),
    QP(5),QP(7),QP(10),QP(10),QP(10),QP(10),QP(10),QP(10),
    QP(10),QP(10),QP(10),QP(10),QP(10),QP(10),QP(10),QP(10),
    QP(10),QP(10),QP(10),QP(10),QP(10),QP(10),QP(10),QP(10),
    QP(10),QP(10),QP(10),QP(10),QP(10),QP(10),QP(10),QP(10),
    QP(10),QP(10),QP(10),QP(10),QP(10),QP(10),QP(10),QP(10)
};

#define IMGW 512
#define TW   64       // tile width (pixels)
#define TH   32       // tile height (pixels)
#define SYS  68       // padded stride of Y plane in smem (64 + 4)
#define SCS  36       // padded stride of chroma planes (32 + 4)
#define NTHR 128

// round-to-nearest-even via magic constant (|x| < 2^22 guaranteed here)
__device__ __forceinline__ float rne(float v) {
    float t = fmaf(v, 1.0f, 12582912.0f);   // 1.5 * 2^23
    return fmaf(t, 1.0f, -12582912.0f);
}

__device__ __forceinline__ void fdct8(const float x[8], float o[8]) {
    float s07 = x[0] + x[7], s16 = x[1] + x[6], s25 = x[2] + x[5], s34 = x[3] + x[4];
    float d07 = x[0] - x[7], d16 = x[1] - x[6], d25 = x[2] - x[5], d34 = x[3] - x[4];
    float e0 = s07 + s34, e1 = s16 + s25, e2 = s07 - s34, e3 = s16 - s25;
    o[0] = G_ * (e0 + e1);
    o[4] = G_ * (e0 - e1);
    o[2] = fmaf( F_, e3, E_ * e2);
    o[6] = fmaf(-E_, e3, F_ * e2);
    o[1] = fmaf( D_, d34, fmaf( C_, d25, fmaf( B_, d16, A_ * d07)));
    o[3] = fmaf(-C_, d34, fmaf(-A_, d25, fmaf(-D_, d16, B_ * d07)));
    o[5] = fmaf( B_, d34, fmaf( D_, d25, fmaf(-A_, d16, C_ * d07)));
    o[7] = fmaf(-A_, d34, fmaf( B_, d25, fmaf(-C_, d16, D_ * d07)));
}

__device__ __forceinline__ void idct8(const float x[8], float o[8]) {
    float ee0 = G_ * (x[0] + x[4]);
    float ee1 = G_ * (x[0] - x[4]);
    float eo0 = fmaf( F_, x[6], E_ * x[2]);
    float eo1 = fmaf(-E_, x[6], F_ * x[2]);
    float ev0 = ee0 + eo0, ev1 = ee1 + eo1, ev2 = ee1 - eo1, ev3 = ee0 - eo0;
    float od0 = fmaf( D_, x[7], fmaf( C_, x[5], fmaf( B_, x[3], A_ * x[1])));
    float od1 = fmaf(-C_, x[7], fmaf(-A_, x[5], fmaf(-D_, x[3], B_ * x[1])));
    float od2 = fmaf( B_, x[7], fmaf( D_, x[5], fmaf(-A_, x[3], C_ * x[1])));
    float od3 = fmaf(-A_, x[7], fmaf( B_, x[5], fmaf(-C_, x[3], D_ * x[1])));
    o[0] = ev0 + od0; o[1] = ev1 + od1; o[2] = ev2 + od2; o[3] = ev3 + od3;
    o[4] = ev3 - od3; o[5] = ev2 - od2; o[6] = ev1 - od1; o[7] = ev0 - od0;
}

// Eklundh 8x8 transpose among 8 lanes (lane = k = tid&7), THREE independent
// blocks interleaved so the shfl latency chains overlap.
__device__ __forceinline__ void transpose8x3(float v0[8], float v1[8], float v2[8],
                                             int k) {
#pragma unroll
    for (int s = 1; s < 8; s <<= 1) {
        const bool up = (k & s) != 0;
#pragma unroll
        for (int j = 0; j < 8; j++) {
            if ((j & s) == 0) {
                const int jp = j | s;
                float s0 = up ? v0[j] : v0[jp];
                float s1 = up ? v1[j] : v1[jp];
                float s2 = up ? v2[j] : v2[jp];
                float r0 = __shfl_xor_sync(0xFFFFFFFFu, s0, s, 32);
                float r1 = __shfl_xor_sync(0xFFFFFFFFu, s1, s, 32);
                float r2 = __shfl_xor_sync(0xFFFFFFFFu, s2, s, 32);
                if (up) { v0[j] = r0; v1[j] = r1; v2[j] = r2; }
                else    { v0[jp] = r0; v1[jp] = r1; v2[jp] = r2; }
            }
        }
    }
}

template <int S>
__device__ __forceinline__ void storerow(float* blk, int k, const float a[8]) {
    *reinterpret_cast<float4*>(blk + k * S)     = make_float4(a[0], a[1], a[2], a[3]);
    *reinterpret_cast<float4*>(blk + k * S + 4) = make_float4(a[4], a[5], a[6], a[7]);
}
template <int S>
__device__ __forceinline__ void loadrow(const float* blk, int k, float a[8]) {
    float4 v0 = *reinterpret_cast<const float4*>(blk + k * S);
    float4 v1 = *reinterpret_cast<const float4*>(blk + k * S + 4);
    a[0] = v0.x; a[1] = v0.y; a[2] = v0.z; a[3] = v0.w;
    a[4] = v1.x; a[5] = v1.y; a[6] = v1.z; a[7] = v1.w;
}

// THREE independent 8x8 blocks (2 luma + 1 chroma) processed concurrently by
// one 8-thread group: triples ILP on the shfl/fma dependency chains.
template <int SL, int SC>
__device__ __forceinline__ void jpeg_block3(float* b0, float* b1, float* b2, int k,
                                            const float2* __restrict__ tabL,
                                            const float2* __restrict__ tabC) {
    float x0[8], x1[8], x2[8], a0[8], a1[8], a2[8];
    loadrow<SL>(b0, k, x0);
    loadrow<SL>(b1, k, x1);
    loadrow<SC>(b2, k, x2);
    fdct8(x0, a0);
    fdct8(x1, a1);
    fdct8(x2, a2);
    transpose8x3(a0, a1, a2, k);
    fdct8(a0, x0);
    fdct8(a1, x1);
    fdct8(a2, x2);
#pragma unroll
    for (int l = 0; l < 8; l++) {
        float2 t = tabL[l * 8 + k];   // shared by both luma blocks
        float2 u = tabC[l * 8 + k];
        x0[l] = rne(x0[l] * t.y) * t.x;
        x1[l] = rne(x1[l] * t.y) * t.x;
        x2[l] = rne(x2[l] * u.y) * u.x;
    }
    idct8(x0, a0);
    idct8(x1, a1);
    idct8(x2, a2);
    transpose8x3(a0, a1, a2, k);
    idct8(a0, x0);
    idct8(a1, x1);
    idct8(a2, x2);
    storerow<SL>(b0, k, x0);
    storerow<SL>(b1, k, x1);
    storerow<SC>(b2, k, x2);
}

// ---------- phase 1 for one tile: LDG.128, x255, RGB->YCbCr, 4:2:0 down ------
__device__ __forceinline__ void phase1(const float* __restrict__ src,
                                       float* __restrict__ sY,
                                       float* __restrict__ sCb,
                                       float* __restrict__ sCr, int tid) {
#pragma unroll
    for (int it = 0; it < 2; it++) {
        int sid = tid + it * NTHR;
        int col = sid & 15, rp = sid >> 4;
        const float* p = src + (rp * 2) * (IMGW * 3) + col * 12;
        float cbs[2] = {0.0f, 0.0f}, crs[2] = {0.0f, 0.0f};
#pragma unroll
        for (int dy = 0; dy < 2; dy++) {
            const float* pr = p + dy * (IMGW * 3);
            float4 q0 = *reinterpret_cast<const float4*>(pr);
            float4 q1 = *reinterpret_cast<const float4*>(pr + 4);
            float4 q2 = *reinterpret_cast<const float4*>(pr + 8);
            float rv[4] = { q0.x, q0.w, q1.z, q2.y };
            float gv[4] = { q0.y, q1.x, q1.w, q2.z };
            float bv[4] = { q0.z, q1.y, q2.x, q2.w };
            float y4[4];
#pragma unroll
            for (int i = 0; i < 4; i++) {
                // input uniform [0,1): floor(x*255) in [0,254], no clip needed
                float r = floorf(rv[i] * 255.0f);
                float g = floorf(gv[i] * 255.0f);
                float b = floorf(bv[i] * 255.0f);
                y4[i] = fmaf(r, 0.299f, fmaf(g, 0.587f, fmaf(b, 0.114f, -128.0f)));
                cbs[i >> 1] += fmaf(r, -0.168736f, fmaf(g, -0.331264f, b * 0.5f));
                crs[i >> 1] += fmaf(r, 0.5f, fmaf(g, -0.418688f, b * (-0.081312f)));
            }
            *reinterpret_cast<float4*>(&sY[(rp * 2 + dy) * SYS + col * 4]) =
                make_float4(y4[0], y4[1], y4[2], y4[3]);
        }
        *reinterpret_cast<float2*>(&sCb[rp * SCS + col * 2]) =
            make_float2(cbs[0] * 0.25f, cbs[1] * 0.25f);
        *reinterpret_cast<float2*>(&sCr[rp * SCS + col * 2]) =
            make_float2(crs[0] * 0.25f, crs[1] * 0.25f);
    }
}

// ---------- phase 2 for one tile: 16 groups x 3 blocks interleaved ----------
__device__ __forceinline__ void phase2(float* __restrict__ sY,
                                       float* __restrict__ sCb,
                                       float* __restrict__ sCr, int tid,
                                       const float2* __restrict__ sTab) {
    const int grp = tid >> 3;   // 0..15
    const int k   = tid & 7;
    const float2* tl = sTab;
    const float2* tc2 = sTab + 64;
    float* yb0 = sY + (grp >> 3) * (8 * SYS) + (grp & 7) * 8;
    float* yb1 = sY + ((grp >> 3) + 2) * (8 * SYS) + (grp & 7) * 8;
    int cg = grp & 7;
    float* cbase = (grp < 8) ? sCb : sCr;
    float* cb = cbase + (cg >> 2) * (8 * SCS) + (cg & 3) * 8;
    jpeg_block3<SYS, SCS>(yb0, yb1, cb, k, tl, tc2);
}

// ---------- phase 3 for one tile: upsample, YCbCr->RGB, clip/round, STG.128 --
__device__ __forceinline__ void phase3(float* __restrict__ dst,
                                       const float* __restrict__ sY,
                                       const float* __restrict__ sCb,
                                       const float* __restrict__ sCr, int tid) {
#pragma unroll
    for (int it = 0; it < 2; it++) {
        int sid = tid + it * NTHR;
        int col = sid & 15, rp = sid >> 4;
        float2 cb2 = *reinterpret_cast<const float2*>(&sCb[rp * SCS + col * 2]);
        float2 cr2 = *reinterpret_cast<const float2*>(&sCr[rp * SCS + col * 2]);
        float cbv[4] = { cb2.x, cb2.x, cb2.y, cb2.y };
        float crv[4] = { cr2.x, cr2.x, cr2.y, cr2.y };
        float* p = dst + (rp * 2) * (IMGW * 3) + col * 12;
#pragma unroll
        for (int dy = 0; dy < 2; dy++) {
            float4 y4 = *reinterpret_cast<const float4*>(&sY[(rp * 2 + dy) * SYS + col * 4]);
            float yv[4] = { y4.x, y4.y, y4.z, y4.w };
            float o[12];
#pragma unroll
            for (int i = 0; i < 4; i++) {
                float y128 = yv[i] + 128.0f;
                float r2 = fmaf(crv[i], 1.402f, y128);
                float g2 = fmaf(cbv[i], -0.344136f, fmaf(crv[i], -0.714136f, y128));
                float b2 = fmaf(cbv[i], 1.772f, y128);
                o[i*3+0] = rne(fminf(fmaxf(r2, 0.0f), 255.0f)) * (1.0f / 255.0f);
                o[i*3+1] = rne(fminf(fmaxf(g2, 0.0f), 255.0f)) * (1.0f / 255.0f);
                o[i*3+2] = rne(fminf(fmaxf(b2, 0.0f), 255.0f)) * (1.0f / 255.0f);
            }
            float* pr = p + dy * (IMGW * 3);
            *reinterpret_cast<float4*>(pr)     = make_float4(o[0], o[1], o[2], o[3]);
            *reinterpret_cast<float4*>(pr + 4) = make_float4(o[4], o[5], o[6], o[7]);
            *reinterpret_cast<float4*>(pr + 8) = make_float4(o[8], o[9], o[10], o[11]);
        }
    }
}

// TWO tiles per CTA (same (x,y), images z and z+16): phases batched so each
// barrier covers both tiles -> half the barriers per tile, double the MLP
// window in the load and store phases.
__global__ void __launch_bounds__(NTHR, 7)
jpeg_kernel(const float* __restrict__ in, float* __restrict__ out) {
    __shared__ float sYa[TH * SYS], sYb[TH * SYS];
    __shared__ float sCba[16 * SCS], sCbb[16 * SCS];
    __shared__ float sCra[16 * SCS], sCrb[16 * SCS];
    __shared__ float2 sTab[128];

    const int tid = threadIdx.x;
    const int tx0 = blockIdx.x * TW;
    const int ty0 = blockIdx.y * TH;
    const int imgA = blockIdx.z;
    const int imgB = blockIdx.z + 16;

    sTab[tid] = c_tab2[tid];   // covered by first barrier

    const float* srcA = in  + (((size_t)imgA * IMGW + ty0) * IMGW + tx0) * 3;
    float*       dstA = out + (((size_t)imgA * IMGW + ty0) * IMGW + tx0) * 3;
    const float* srcB = in  + (((size_t)imgB * IMGW + ty0) * IMGW + tx0) * 3;
    float*       dstB = out + (((size_t)imgB * IMGW + ty0) * IMGW + tx0) * 3;

    phase1(srcA, sYa, sCba, sCra, tid);
    phase1(srcB, sYb, sCbb, sCrb, tid);
    __syncthreads();

    phase2(sYa, sCba, sCra, tid, sTab);
    phase2(sYb, sCbb, sCrb, tid, sTab);
    __syncthreads();

    phase3(dstA, sYa, sCba, sCra, tid);
    phase3(dstB, sYb, sCbb, sCrb, tid);
}

extern "C" void kernel_launch(void* const* d_in, const int* in_sizes, int n_in,
                              void* d_out, int out_size) {
    (void)in_sizes; (void)n_in; (void)out_size;
    dim3 grid(IMGW / TW, IMGW / TH, 16);
    jpeg_kernel<<<grid, NTHR>>>((const float*)d_in[0], (float*)d_out);
}

// round 15
// speedup vs baseline: 1.2893x; 1.1742x over previous
#include <cuda_runtime.h>

// ---------------- DCT-II 8-point constants (fp32, match np.float32(D)) ----
#define G_ 0.35355339059327373f
#define A_ 0.49039264020161522f
#define B_ 0.41573480615127262f
#define C_ 0.27778511650980114f
#define D_ 0.09754516100806417f
#define E_ 0.46193976625564337f
#define F_ 0.19134171618254492f

// Quant tables for QUALITY=95 in NATURAL layout, packed (q, 1/q).
#define QP(v) {(float)(v), 1.0f/(float)(v)}
__constant__ float2 c_tab2[128] = {
    // luma (natural row-major)
    QP(2),QP(1),QP(1),QP(2),QP(2),QP(4),QP(5),QP(6),
    QP(1),QP(1),QP(1),QP(2),QP(3),QP(6),QP(6),QP(6),
    QP(1),QP(1),QP(2),QP(2),QP(4),QP(6),QP(7),QP(6),
    QP(1),QP(2),QP(2),QP(3),QP(5),QP(9),QP(8),QP(6),
    QP(2),QP(2),QP(4),QP(6),QP(7),QP(11),QP(10),QP(8),
    QP(2),QP(4),QP(6),QP(6),QP(8),QP(10),QP(11),QP(9),
    QP(5),QP(6),QP(8),QP(9),QP(10),QP(12),QP(12),QP(10),
    QP(7),QP(9),QP(10),QP(10),QP(11),QP(10),QP(10),QP(10),
    // chroma (natural row-major, symmetric)
    QP(2),QP(2),QP(2),QP(5),QP(10),QP(10),QP(10),QP(10),
    QP(2),QP(2),QP(3),QP(7),QP(10),QP(10),QP(10),QP(10),
    QP(2),QP(3),QP(6),QP(10),QP(10),QP(10),QP(10),QP(10),
    QP(5),QP(7),QP(10),QP(10),QP(10),QP(10),QP(10),QP(10),
    QP(10),QP(10),QP(10),QP(10),QP(10),QP(10),QP(10),QP(10),
    QP(10),QP(10),QP(10),QP(10),QP(10),QP(10),QP(10),QP(10),
    QP(10),QP(10),QP(10),QP(10),QP(10),QP(10),QP(10),QP(10),
    QP(10),QP(10),QP(10),QP(10),QP(10),QP(10),QP(10),QP(10)
};

#define IMGW 512
#define TW   32       // tile width (pixels)
#define TH   32       // tile height (pixels)
#define SYS  36       // padded stride of Y plane in smem (32 + 4)
#define SCS  20       // padded stride of chroma planes (16 + 4)
#define NTHR 64

// round-to-nearest-even via magic constant (|x| < 2^22 guaranteed here)
__device__ __forceinline__ float rne(float v) {
    float t = fmaf(v, 1.0f, 12582912.0f);   // 1.5 * 2^23
    return fmaf(t, 1.0f, -12582912.0f);
}

__device__ __forceinline__ void fdct8(const float x[8], float o[8]) {
    float s07 = x[0] + x[7], s16 = x[1] + x[6], s25 = x[2] + x[5], s34 = x[3] + x[4];
    float d07 = x[0] - x[7], d16 = x[1] - x[6], d25 = x[2] - x[5], d34 = x[3] - x[4];
    float e0 = s07 + s34, e1 = s16 + s25, e2 = s07 - s34, e3 = s16 - s25;
    o[0] = G_ * (e0 + e1);
    o[4] = G_ * (e0 - e1);
    o[2] = fmaf( F_, e3, E_ * e2);
    o[6] = fmaf(-E_, e3, F_ * e2);
    o[1] = fmaf( D_, d34, fmaf( C_, d25, fmaf( B_, d16, A_ * d07)));
    o[3] = fmaf(-C_, d34, fmaf(-A_, d25, fmaf(-D_, d16, B_ * d07)));
    o[5] = fmaf( B_, d34, fmaf( D_, d25, fmaf(-A_, d16, C_ * d07)));
    o[7] = fmaf(-A_, d34, fmaf( B_, d25, fmaf(-C_, d16, D_ * d07)));
}

__device__ __forceinline__ void idct8(const float x[8], float o[8]) {
    float ee0 = G_ * (x[0] + x[4]);
    float ee1 = G_ * (x[0] - x[4]);
    float eo0 = fmaf( F_, x[6], E_ * x[2]);
    float eo1 = fmaf(-E_, x[6], F_ * x[2]);
    float ev0 = ee0 + eo0, ev1 = ee1 + eo1, ev2 = ee1 - eo1, ev3 = ee0 - eo0;
    float od0 = fmaf( D_, x[7], fmaf( C_, x[5], fmaf( B_, x[3], A_ * x[1])));
    float od1 = fmaf(-C_, x[7], fmaf(-A_, x[5], fmaf(-D_, x[3], B_ * x[1])));
    float od2 = fmaf( B_, x[7], fmaf( D_, x[5], fmaf(-A_, x[3], C_ * x[1])));
    float od3 = fmaf(-A_, x[7], fmaf( B_, x[5], fmaf(-C_, x[3], D_ * x[1])));
    o[0] = ev0 + od0; o[1] = ev1 + od1; o[2] = ev2 + od2; o[3] = ev3 + od3;
    o[4] = ev3 - od3; o[5] = ev2 - od2; o[6] = ev1 - od1; o[7] = ev0 - od0;
}

// Eklundh 8x8 transpose among 8 lanes (lane = k = tid&7), THREE independent
// blocks interleaved so the shfl latency chains overlap.
__device__ __forceinline__ void transpose8x3(float v0[8], float v1[8], float v2[8],
                                             int k) {
#pragma unroll
    for (int s = 1; s < 8; s <<= 1) {
        const bool up = (k & s) != 0;
#pragma unroll
        for (int j = 0; j < 8; j++) {
            if ((j & s) == 0) {
                const int jp = j | s;
                float s0 = up ? v0[j] : v0[jp];
                float s1 = up ? v1[j] : v1[jp];
                float s2 = up ? v2[j] : v2[jp];
                float r0 = __shfl_xor_sync(0xFFFFFFFFu, s0, s, 32);
                float r1 = __shfl_xor_sync(0xFFFFFFFFu, s1, s, 32);
                float r2 = __shfl_xor_sync(0xFFFFFFFFu, s2, s, 32);
                if (up) { v0[j] = r0; v1[j] = r1; v2[j] = r2; }
                else    { v0[jp] = r0; v1[jp] = r1; v2[jp] = r2; }
            }
        }
    }
}

template <int S>
__device__ __forceinline__ void storerow(float* blk, int k, const float a[8]) {
    *reinterpret_cast<float4*>(blk + k * S)     = make_float4(a[0], a[1], a[2], a[3]);
    *reinterpret_cast<float4*>(blk + k * S + 4) = make_float4(a[4], a[5], a[6], a[7]);
}
template <int S>
__device__ __forceinline__ void loadrow(const float* blk, int k, float a[8]) {
    float4 v0 = *reinterpret_cast<const float4*>(blk + k * S);
    float4 v1 = *reinterpret_cast<const float4*>(blk + k * S + 4);
    a[0] = v0.x; a[1] = v0.y; a[2] = v0.z; a[3] = v0.w;
    a[4] = v1.x; a[5] = v1.y; a[6] = v1.z; a[7] = v1.w;
}

// THREE independent 8x8 blocks (2 luma + 1 chroma) processed concurrently by
// one 8-thread group: triples ILP on the shfl/fma dependency chains.
template <int SL, int SC>
__device__ __forceinline__ void jpeg_block3(float* b0, float* b1, float* b2, int k,
                                            const float2* __restrict__ tabL,
                                            const float2* __restrict__ tabC) {
    float x0[8], x1[8], x2[8], a0[8], a1[8], a2[8];
    loadrow<SL>(b0, k, x0);
    loadrow<SL>(b1, k, x1);
    loadrow<SC>(b2, k, x2);
    fdct8(x0, a0);
    fdct8(x1, a1);
    fdct8(x2, a2);
    transpose8x3(a0, a1, a2, k);
    fdct8(a0, x0);
    fdct8(a1, x1);
    fdct8(a2, x2);
#pragma unroll
    for (int l = 0; l < 8; l++) {
        float2 t = tabL[l * 8 + k];   // shared by both luma blocks
        float2 u = tabC[l * 8 + k];
        x0[l] = rne(x0[l] * t.y) * t.x;
        x1[l] = rne(x1[l] * t.y) * t.x;
        x2[l] = rne(x2[l] * u.y) * u.x;
    }
    idct8(x0, a0);
    idct8(x1, a1);
    idct8(x2, a2);
    transpose8x3(a0, a1, a2, k);
    idct8(a0, x0);
    idct8(a1, x1);
    idct8(a2, x2);
    storerow<SL>(b0, k, x0);
    storerow<SL>(b1, k, x1);
    storerow<SC>(b2, k, x2);
}

__global__ void __launch_bounds__(NTHR, 14)
jpeg_kernel(const float* __restrict__ in, float* __restrict__ out) {
    __shared__ float sY[TH * SYS];           // 32 x 36
    __shared__ float sCb[16 * SCS];          // 16 x 20 (chroma 16x16)
    __shared__ float sCr[16 * SCS];
    __shared__ float2 sTab[128];

    const int tid = threadIdx.x;
    const int tx0 = blockIdx.x * TW;
    const int ty0 = blockIdx.y * TH;
    const int img = blockIdx.z;

    sTab[tid] = c_tab2[tid];                 // 64 threads, 2 rounds for 128
    sTab[NTHR + tid] = c_tab2[NTHR + tid];

    const float* src = in  + (((size_t)img * IMGW + ty0) * IMGW + tx0) * 3;
    float*       dst = out + (((size_t)img * IMGW + ty0) * IMGW + tx0) * 3;

    // ---------- phase 1: LDG.128, x255, RGB->YCbCr, 4:2:0 downsample ----------
    // Region = 4px wide x 2 rows. 8 col-groups x 16 row-pairs = 128 regions,
    // exactly 2 uniform iterations at 64 threads.
#pragma unroll
    for (int it = 0; it < 2; it++) {
        int sid = tid + it * NTHR;
        int col = sid & 7, rp = sid >> 3;
        const float* p = src + (rp * 2) * (IMGW * 3) + col * 12;
        float cbs[2] = {0.0f, 0.0f}, crs[2] = {0.0f, 0.0f};
#pragma unroll
        for (int dy = 0; dy < 2; dy++) {
            const float* pr = p + dy * (IMGW * 3);
            float4 q0 = *reinterpret_cast<const float4*>(pr);
            float4 q1 = *reinterpret_cast<const float4*>(pr + 4);
            float4 q2 = *reinterpret_cast<const float4*>(pr + 8);
            float rv[4] = { q0.x, q0.w, q1.z, q2.y };
            float gv[4] = { q0.y, q1.x, q1.w, q2.z };
            float bv[4] = { q0.z, q1.y, q2.x, q2.w };
            float y4[4];
#pragma unroll
            for (int i = 0; i < 4; i++) {
                // input uniform [0,1): floor(x*255) in [0,254], no clip needed
                float r = floorf(rv[i] * 255.0f);
                float g = floorf(gv[i] * 255.0f);
                float b = floorf(bv[i] * 255.0f);
                y4[i] = fmaf(r, 0.299f, fmaf(g, 0.587f, fmaf(b, 0.114f, -128.0f)));
                cbs[i >> 1] += fmaf(r, -0.168736f, fmaf(g, -0.331264f, b * 0.5f));
                crs[i >> 1] += fmaf(r, 0.5f, fmaf(g, -0.418688f, b * (-0.081312f)));
            }
            *reinterpret_cast<float4*>(&sY[(rp * 2 + dy) * SYS + col * 4]) =
                make_float4(y4[0], y4[1], y4[2], y4[3]);
        }
        *reinterpret_cast<float2*>(&sCb[rp * SCS + col * 2]) =
            make_float2(cbs[0] * 0.25f, cbs[1] * 0.25f);
        *reinterpret_cast<float2*>(&sCr[rp * SCS + col * 2]) =
            make_float2(crs[0] * 0.25f, crs[1] * 0.25f);
    }
    __syncthreads();

    // ---------- phase 2: 8 groups x 3 blocks (2 luma + 1 chroma) interleaved --
    {
        const int grp = tid >> 3;   // 0..7
        const int k   = tid & 7;

        const float2* tl = sTab;        // luma (q, 1/q) natural layout
        const float2* tc2 = sTab + 64;  // chroma

        // luma: 4 block-cols x 4 block-rows; group handles rows (grp>>2) and +2
        float* yb0 = sY + (grp >> 2) * (8 * SYS) + (grp & 3) * 8;
        float* yb1 = sY + ((grp >> 2) + 2) * (8 * SYS) + (grp & 3) * 8;

        // chroma: 2 block-cols x 2 block-rows per plane; grp<4 -> Cb, else Cr
        int cg = grp & 3;
        float* cbase = (grp < 4) ? sCb : sCr;
        float* cb = cbase + (cg >> 1) * (8 * SCS) + (cg & 1) * 8;

        jpeg_block3<SYS, SCS>(yb0, yb1, cb, k, tl, tc2);
    }
    __syncthreads();

    // ---------- phase 3: upsample chroma, YCbCr->RGB, clip, round, STG.128 ----
#pragma unroll
    for (int it = 0; it < 2; it++) {
        int sid = tid + it * NTHR;
        int col = sid & 7, rp = sid >> 3;
        float2 cb2 = *reinterpret_cast<const float2*>(&sCb[rp * SCS + col * 2]);
        float2 cr2 = *reinterpret_cast<const float2*>(&sCr[rp * SCS + col * 2]);
        float cbv[4] = { cb2.x, cb2.x, cb2.y, cb2.y };
        float crv[4] = { cr2.x, cr2.x, cr2.y, cr2.y };
        float* p = dst + (rp * 2) * (IMGW * 3) + col * 12;
#pragma unroll
        for (int dy = 0; dy < 2; dy++) {
            float4 y4 = *reinterpret_cast<const float4*>(&sY[(rp * 2 + dy) * SYS + col * 4]);
            float yv[4] = { y4.x, y4.y, y4.z, y4.w };
            float o[12];
#pragma unroll
            for (int i = 0; i < 4; i++) {
                float y128 = yv[i] + 128.0f;
                float r2 = fmaf(crv[i], 1.402f, y128);
                float g2 = fmaf(cbv[i], -0.344136f, fmaf(crv[i], -0.714136f, y128));
                float b2 = fmaf(cbv[i], 1.772f, y128);
                o[i*3+0] = rne(fminf(fmaxf(r2, 0.0f), 255.0f)) * (1.0f / 255.0f);
                o[i*3+1] = rne(fminf(fmaxf(g2, 0.0f), 255.0f)) * (1.0f / 255.0f);
                o[i*3+2] = rne(fminf(fmaxf(b2, 0.0f), 255.0f)) * (1.0f / 255.0f);
            }
            float* pr = p + dy * (IMGW * 3);
            *reinterpret_cast<float4*>(pr)     = make_float4(o[0], o[1], o[2], o[3]);
            *reinterpret_cast<float4*>(pr + 4) = make_float4(o[4], o[5], o[6], o[7]);
            *reinterpret_cast<float4*>(pr + 8) = make_float4(o[8], o[9], o[10], o[11]);
        }
    }
}

extern "C" void kernel_launch(void* const* d_in, const int* in_sizes, int n_in,
                              void* d_out, int out_size) {
    (void)in_sizes; (void)n_in; (void)out_size;
    dim3 grid(IMGW / TW, IMGW / TH, 32);
    jpeg_kernel<<<grid, NTHR>>>((const float*)d_in[0], (float*)d_out);
}

// round 16
// speedup vs baseline: 1.3084x; 1.0148x over previous
#include <cuda_runtime.h>

// ---------------- DCT-II 8-point constants (fp32, match np.float32(D)) ----
#define G_ 0.35355339059327373f
#define A_ 0.49039264020161522f
#define B_ 0.41573480615127262f
#define C_ 0.27778511650980114f
#define D_ 0.09754516100806417f
#define E_ 0.46193976625564337f
#define F_ 0.19134171618254492f

// Quant tables for QUALITY=95 in NATURAL layout, packed (q, 1/q).
#define QP(v) {(float)(v), 1.0f/(float)(v)}
__constant__ float2 c_tab2[128] = {
    // luma (natural row-major)
    QP(2),QP(1),QP(1),QP(2),QP(2),QP(4),QP(5),QP(6),
    QP(1),QP(1),QP(1),QP(2),QP(3),QP(6),QP(6),QP(6),
    QP(1),QP(1),QP(2),QP(2),QP(4),QP(6),QP(7),QP(6),
    QP(1),QP(2),QP(2),QP(3),QP(5),QP(9),QP(8),QP(6),
    QP(2),QP(2),QP(4),QP(6),QP(7),QP(11),QP(10),QP(8),
    QP(2),QP(4),QP(6),QP(6),QP(8),QP(10),QP(11),QP(9),
    QP(5),QP(6),QP(8),QP(9),QP(10),QP(12),QP(12),QP(10),
    QP(7),QP(9),QP(10),QP(10),QP(11),QP(10),QP(10),QP(10),
    // chroma (natural row-major, symmetric)
    QP(2),QP(2),QP(2),QP(5),QP(10),QP(10),QP(10),QP(10),
    QP(2),QP(2),QP(3),QP(7),QP(10),QP(10),QP(10),QP(10),
    QP(2),QP(3),QP(6),QP(10),QP(10),QP(10),QP(10),QP(10),
    QP(5),QP(7),QP(10),QP(10),QP(10),QP(10),QP(10),QP(10),
    QP(10),QP(10),QP(10),QP(10),QP(10),QP(10),QP(10),QP(10),
    QP(10),QP(10),QP(10),QP(10),QP(10),QP(10),QP(10),QP(10),
    QP(10),QP(10),QP(10),QP(10),QP(10),QP(10),QP(10),QP(10),
    QP(10),QP(10),QP(10),QP(10),QP(10),QP(10),QP(10),QP(10)
};

#define IMGW 512
#define TW   64       // tile width (pixels)
#define TH   32       // tile height (pixels)
#define SYS  68       // padded stride of Y plane in smem (64 + 4)
#define SCS  36       // padded stride of chroma planes (32 + 4)
#define NTHR 128

// round-to-nearest-even via magic constant (|x| < 2^22 guaranteed here)
__device__ __forceinline__ float rne(float v) {
    float t = fmaf(v, 1.0f, 12582912.0f);   // 1.5 * 2^23
    return fmaf(t, 1.0f, -12582912.0f);
}

__device__ __forceinline__ void fdct8(const float x[8], float o[8]) {
    float s07 = x[0] + x[7], s16 = x[1] + x[6], s25 = x[2] + x[5], s34 = x[3] + x[4];
    float d07 = x[0] - x[7], d16 = x[1] - x[6], d25 = x[2] - x[5], d34 = x[3] - x[4];
    float e0 = s07 + s34, e1 = s16 + s25, e2 = s07 - s34, e3 = s16 - s25;
    o[0] = G_ * (e0 + e1);
    o[4] = G_ * (e0 - e1);
    o[2] = fmaf( F_, e3, E_ * e2);
    o[6] = fmaf(-E_, e3, F_ * e2);
    o[1] = fmaf( D_, d34, fmaf( C_, d25, fmaf( B_, d16, A_ * d07)));
    o[3] = fmaf(-C_, d34, fmaf(-A_, d25, fmaf(-D_, d16, B_ * d07)));
    o[5] = fmaf( B_, d34, fmaf( D_, d25, fmaf(-A_, d16, C_ * d07)));
    o[7] = fmaf(-A_, d34, fmaf( B_, d25, fmaf(-C_, d16, D_ * d07)));
}

__device__ __forceinline__ void idct8(const float x[8], float o[8]) {
    float ee0 = G_ * (x[0] + x[4]);
    float ee1 = G_ * (x[0] - x[4]);
    float eo0 = fmaf( F_, x[6], E_ * x[2]);
    float eo1 = fmaf(-E_, x[6], F_ * x[2]);
    float ev0 = ee0 + eo0, ev1 = ee1 + eo1, ev2 = ee1 - eo1, ev3 = ee0 - eo0;
    float od0 = fmaf( D_, x[7], fmaf( C_, x[5], fmaf( B_, x[3], A_ * x[1])));
    float od1 = fmaf(-C_, x[7], fmaf(-A_, x[5], fmaf(-D_, x[3], B_ * x[1])));
    float od2 = fmaf( B_, x[7], fmaf( D_, x[5], fmaf(-A_, x[3], C_ * x[1])));
    float od3 = fmaf(-A_, x[7], fmaf( B_, x[5], fmaf(-C_, x[3], D_ * x[1])));
    o[0] = ev0 + od0; o[1] = ev1 + od1; o[2] = ev2 + od2; o[3] = ev3 + od3;
    o[4] = ev3 - od3; o[5] = ev2 - od2; o[6] = ev1 - od1; o[7] = ev0 - od0;
}

// Eklundh 8x8 transpose among 8 lanes (lane = k = tid&7), THREE independent
// blocks interleaved so the shfl latency chains overlap.
__device__ __forceinline__ void transpose8x3(float v0[8], float v1[8], float v2[8],
                                             int k) {
#pragma unroll
    for (int s = 1; s < 8; s <<= 1) {
        const bool up = (k & s) != 0;
#pragma unroll
        for (int j = 0; j < 8; j++) {
            if ((j & s) == 0) {
                const int jp = j | s;
                float s0 = up ? v0[j] : v0[jp];
                float s1 = up ? v1[j] : v1[jp];
                float s2 = up ? v2[j] : v2[jp];
                float r0 = __shfl_xor_sync(0xFFFFFFFFu, s0, s, 32);
                float r1 = __shfl_xor_sync(0xFFFFFFFFu, s1, s, 32);
                float r2 = __shfl_xor_sync(0xFFFFFFFFu, s2, s, 32);
                if (up) { v0[j] = r0; v1[j] = r1; v2[j] = r2; }
                else    { v0[jp] = r0; v1[jp] = r1; v2[jp] = r2; }
            }
        }
    }
}

template <int S>
__device__ __forceinline__ void storerow(float* blk, int k, const float a[8]) {
    *reinterpret_cast<float4*>(blk + k * S)     = make_float4(a[0], a[1], a[2], a[3]);
    *reinterpret_cast<float4*>(blk + k * S + 4) = make_float4(a[4], a[5], a[6], a[7]);
}
template <int S>
__device__ __forceinline__ void loadrow(const float* blk, int k, float a[8]) {
    float4 v0 = *reinterpret_cast<const float4*>(blk + k * S);
    float4 v1 = *reinterpret_cast<const float4*>(blk + k * S + 4);
    a[0] = v0.x; a[1] = v0.y; a[2] = v0.z; a[3] = v0.w;
    a[4] = v1.x; a[5] = v1.y; a[6] = v1.z; a[7] = v1.w;
}

// THREE independent 8x8 blocks (2 luma + 1 chroma) processed concurrently by
// one 8-thread group: triples ILP on the shfl/fma dependency chains.
template <int SL, int SC>
__device__ __forceinline__ void jpeg_block3(float* b0, float* b1, float* b2, int k,
                                            const float2* __restrict__ tabL,
                                            const float2* __restrict__ tabC) {
    float x0[8], x1[8], x2[8], a0[8], a1[8], a2[8];
    loadrow<SL>(b0, k, x0);
    loadrow<SL>(b1, k, x1);
    loadrow<SC>(b2, k, x2);
    fdct8(x0, a0);
    fdct8(x1, a1);
    fdct8(x2, a2);
    transpose8x3(a0, a1, a2, k);
    fdct8(a0, x0);
    fdct8(a1, x1);
    fdct8(a2, x2);
#pragma unroll
    for (int l = 0; l < 8; l++) {
        float2 t = tabL[l * 8 + k];   // shared by both luma blocks
        float2 u = tabC[l * 8 + k];
        x0[l] = rne(x0[l] * t.y) * t.x;
        x1[l] = rne(x1[l] * t.y) * t.x;
        x2[l] = rne(x2[l] * u.y) * u.x;
    }
    idct8(x0, a0);
    idct8(x1, a1);
    idct8(x2, a2);
    transpose8x3(a0, a1, a2, k);
    idct8(a0, x0);
    idct8(a1, x1);
    idct8(a2, x2);
    storerow<SL>(b0, k, x0);
    storerow<SL>(b1, k, x1);
    storerow<SC>(b2, k, x2);
}

__global__ void __launch_bounds__(NTHR, 7)
jpeg_kernel(const float* __restrict__ in, float* __restrict__ out) {
    __shared__ float sY[TH * SYS];           // 32 x 68
    __shared__ float sCb[16 * SCS];          // 16 x 36 (chroma 32x16)
    __shared__ float sCr[16 * SCS];
    __shared__ float2 sTab[128];

    const int tid = threadIdx.x;
    const int tx0 = blockIdx.x * TW;
    const int ty0 = blockIdx.y * TH;
    const int img = blockIdx.z;

    sTab[tid] = c_tab2[tid];   // 128 threads cover 128 entries; phase-1 barrier

    const float* src = in  + (((size_t)img * IMGW + ty0) * IMGW + tx0) * 3;
    float*       dst = out + (((size_t)img * IMGW + ty0) * IMGW + tx0) * 3;

    // ---------- phase 1: LDG.128 (all 6 per iteration issued UP FRONT, MLP=6),
    // x255, RGB->YCbCr, 4:2:0 downsample. Region = 4px wide x 2 rows.
#pragma unroll
    for (int it = 0; it < 2; it++) {
        int sid = tid + it * NTHR;
        int col = sid & 15, rp = sid >> 4;
        const float* p = src + (rp * 2) * (IMGW * 3) + col * 12;
        const float* pr0 = p;
        const float* pr1 = p + (IMGW * 3);

        // issue ALL six 16B loads before any math: doubles the in-flight
        // window vs the interleaved form (lat/MLP halves the exposure)
        float4 qa0 = *reinterpret_cast<const float4*>(pr0);
        float4 qa1 = *reinterpret_cast<const float4*>(pr0 + 4);
        float4 qa2 = *reinterpret_cast<const float4*>(pr0 + 8);
        float4 qb0 = *reinterpret_cast<const float4*>(pr1);
        float4 qb1 = *reinterpret_cast<const float4*>(pr1 + 4);
        float4 qb2 = *reinterpret_cast<const float4*>(pr1 + 8);

        float cbs[2] = {0.0f, 0.0f}, crs[2] = {0.0f, 0.0f};
#pragma unroll
        for (int dy = 0; dy < 2; dy++) {
            float4 q0 = dy ? qb0 : qa0;
            float4 q1 = dy ? qb1 : qa1;
            float4 q2 = dy ? qb2 : qa2;
            float rv[4] = { q0.x, q0.w, q1.z, q2.y };
            float gv[4] = { q0.y, q1.x, q1.w, q2.z };
            float bv[4] = { q0.z, q1.y, q2.x, q2.w };
            float y4[4];
#pragma unroll
            for (int i = 0; i < 4; i++) {
                // input uniform [0,1): floor(x*255) in [0,254], no clip needed
                float r = floorf(rv[i] * 255.0f);
                float g = floorf(gv[i] * 255.0f);
                float b = floorf(bv[i] * 255.0f);
                y4[i] = fmaf(r, 0.299f, fmaf(g, 0.587f, fmaf(b, 0.114f, -128.0f)));
                cbs[i >> 1] += fmaf(r, -0.168736f, fmaf(g, -0.331264f, b * 0.5f));
                crs[i >> 1] += fmaf(r, 0.5f, fmaf(g, -0.418688f, b * (-0.081312f)));
            }
            *reinterpret_cast<float4*>(&sY[(rp * 2 + dy) * SYS + col * 4]) =
                make_float4(y4[0], y4[1], y4[2], y4[3]);
        }
        *reinterpret_cast<float2*>(&sCb[rp * SCS + col * 2]) =
            make_float2(cbs[0] * 0.25f, cbs[1] * 0.25f);
        *reinterpret_cast<float2*>(&sCr[rp * SCS + col * 2]) =
            make_float2(crs[0] * 0.25f, crs[1] * 0.25f);
    }
    __syncthreads();

    // ---------- phase 2: 16 groups x 3 blocks (2 luma + 1 chroma) interleaved --
    {
        const int grp = tid >> 3;   // 0..15
        const int k   = tid & 7;

        const float2* tl = sTab;        // luma (q, 1/q) natural layout
        const float2* tc2 = sTab + 64;  // chroma

        // luma: 8 block-cols x 4 block-rows; group handles rows (grp>>3) and +2
        float* yb0 = sY + (grp >> 3) * (8 * SYS) + (grp & 7) * 8;
        float* yb1 = sY + ((grp >> 3) + 2) * (8 * SYS) + (grp & 7) * 8;

        // chroma: 4 block-cols x 2 block-rows per plane; grp<8 -> Cb, else Cr
        int cg = grp & 7;
        float* cbase = (grp < 8) ? sCb : sCr;
        float* cb = cbase + (cg >> 2) * (8 * SCS) + (cg & 3) * 8;

        jpeg_block3<SYS, SCS>(yb0, yb1, cb, k, tl, tc2);
    }
    __syncthreads();

    // ---------- phase 3: upsample chroma, YCbCr->RGB, clip, round, STG.128 ----
#pragma unroll
    for (int it = 0; it < 2; it++) {
        int sid = tid + it * NTHR;
        int col = sid & 15, rp = sid >> 4;
        float2 cb2 = *reinterpret_cast<const float2*>(&sCb[rp * SCS + col * 2]);
        float2 cr2 = *reinterpret_cast<const float2*>(&sCr[rp * SCS + col * 2]);
        float cbv[4] = { cb2.x, cb2.x, cb2.y, cb2.y };
        float crv[4] = { cr2.x, cr2.x, cr2.y, cr2.y };
        float* p = dst + (rp * 2) * (IMGW * 3) + col * 12;
#pragma unroll
        for (int dy = 0; dy < 2; dy++) {
            float4 y4 = *reinterpret_cast<const float4*>(&sY[(rp * 2 + dy) * SYS + col * 4]);
            float yv[4] = { y4.x, y4.y, y4.z, y4.w };
            float o[12];
#pragma unroll
            for (int i = 0; i < 4; i++) {
                float y128 = yv[i] + 128.0f;
                float r2 = fmaf(crv[i], 1.402f, y128);
                float g2 = fmaf(cbv[i], -0.344136f, fmaf(crv[i], -0.714136f, y128));
                float b2 = fmaf(cbv[i], 1.772f, y128);
                o[i*3+0] = rne(fminf(fmaxf(r2, 0.0f), 255.0f)) * (1.0f / 255.0f);
                o[i*3+1] = rne(fminf(fmaxf(g2, 0.0f), 255.0f)) * (1.0f / 255.0f);
                o[i*3+2] = rne(fminf(fmaxf(b2, 0.0f), 255.0f)) * (1.0f / 255.0f);
            }
            float* pr = p + dy * (IMGW * 3);
            *reinterpret_cast<float4*>(pr)     = make_float4(o[0], o[1], o[2], o[3]);
            *reinterpret_cast<float4*>(pr + 4) = make_float4(o[4], o[5], o[6], o[7]);
            *reinterpret_cast<float4*>(pr + 8) = make_float4(o[8], o[9], o[10], o[11]);
        }
    }
}

extern "C" void kernel_launch(void* const* d_in, const int* in_sizes, int n_in,
                              void* d_out, int out_size) {
    (void)in_sizes; (void)n_in; (void)out_size;
    dim3 grid(IMGW / TW, IMGW / TH, 32);
    jpeg_kernel<<<grid, NTHR>>>((const float*)d_in[0], (float*)d_out);
}

// round 17
// speedup vs baseline: 1.3094x; 1.0008x over previous
#include <cuda_runtime.h>

// ---------------- DCT-II 8-point constants (fp32, match np.float32(D)) ----
#define G_ 0.35355339059327373f
#define A_ 0.49039264020161522f
#define B_ 0.41573480615127262f
#define C_ 0.27778511650980114f
#define D_ 0.09754516100806417f
#define E_ 0.46193976625564337f
#define F_ 0.19134171618254492f

#define MAGIC 12582912.0f   // 1.5 * 2^23

// Quant tables for QUALITY=95 in NATURAL layout, packed (q, 1/q).
#define QP(v) {(float)(v), 1.0f/(float)(v)}
__constant__ float2 c_tab2[128] = {
    // luma (natural row-major)
    QP(2),QP(1),QP(1),QP(2),QP(2),QP(4),QP(5),QP(6),
    QP(1),QP(1),QP(1),QP(2),QP(3),QP(6),QP(6),QP(6),
    QP(1),QP(1),QP(2),QP(2),QP(4),QP(6),QP(7),QP(6),
    QP(1),QP(2),QP(2),QP(3),QP(5),QP(9),QP(8),QP(6),
    QP(2),QP(2),QP(4),QP(6),QP(7),QP(11),QP(10),QP(8),
    QP(2),QP(4),QP(6),QP(6),QP(8),QP(10),QP(11),QP(9),
    QP(5),QP(6),QP(8),QP(9),QP(10),QP(12),QP(12),QP(10),
    QP(7),QP(9),QP(10),QP(10),QP(11),QP(10),QP(10),QP(10),
    // chroma (natural row-major, symmetric)
    QP(2),QP(2),QP(2),QP(5),QP(10),QP(10),QP(10),QP(10),
    QP(2),QP(2),QP(3),QP(7),QP(10),QP(10),QP(10),QP(10),
    QP(2),QP(3),QP(6),QP(10),QP(10),QP(10),QP(10),QP(10),
    QP(5),QP(7),QP(10),QP(10),QP(10),QP(10),QP(10),QP(10),
    QP(10),QP(10),QP(10),QP(10),QP(10),QP(10),QP(10),QP(10),
    QP(10),QP(10),QP(10),QP(10),QP(10),QP(10),QP(10),QP(10),
    QP(10),QP(10),QP(10),QP(10),QP(10),QP(10),QP(10),QP(10),
    QP(10),QP(10),QP(10),QP(10),QP(10),QP(10),QP(10),QP(10)
};

#define IMGW 512
#define TW   64
#define TH   32
#define SYS  68
#define SCS  36
#define NTHR 128

typedef unsigned long long u64;

// ---------------- packed f32x2 primitives (sm_103a FFMA2 path) -----------
__device__ __forceinline__ u64 pk2(float lo, float hi) {
    u64 r;
    asm("mov.b64 %0, {%1, %2};" : "=l"(r)
        : "r"(__float_as_uint(lo)), "r"(__float_as_uint(hi)));
    return r;
}
__device__ __forceinline__ void upk2(u64 v, float& lo, float& hi) {
    unsigned a, b;
    asm("mov.b64 {%0, %1}, %2;" : "=r"(a), "=r"(b) : "l"(v));
    lo = __uint_as_float(a); hi = __uint_as_float(b);
}
__device__ __forceinline__ u64 bc2(float c) { return pk2(c, c); }
__device__ __forceinline__ u64 add2(u64 a, u64 b) {
    u64 r; asm("add.rn.f32x2 %0, %1, %2;" : "=l"(r) : "l"(a), "l"(b)); return r;
}
__device__ __forceinline__ u64 mul2(u64 a, u64 b) {
    u64 r; asm("mul.rn.f32x2 %0, %1, %2;" : "=l"(r) : "l"(a), "l"(b)); return r;
}
__device__ __forceinline__ u64 fma2(u64 a, u64 b, u64 c) {
    u64 r; asm("fma.rn.f32x2 %0, %1, %2, %3;" : "=l"(r) : "l"(a), "l"(b), "l"(c)); return r;
}

struct PK { u64 G, A, B, C, D, E, F, M1, MG; };
__device__ __forceinline__ PK mkpk() {
    PK p;
    p.G = bc2(G_); p.A = bc2(A_); p.B = bc2(B_); p.C = bc2(C_); p.D = bc2(D_);
    p.E = bc2(E_); p.F = bc2(F_); p.M1 = bc2(-1.0f); p.MG = bc2(MAGIC);
    return p;
}

// Packed forward DCT on two blocks at once. Subtractions via fma(x,-1,y)
// (exact); sign-mixed rows re-associated to reuse positive constants.
__device__ __forceinline__ void fdct8p(const u64 x[8], u64 o[8], const PK& p) {
    u64 s07 = add2(x[0], x[7]), s16 = add2(x[1], x[6]);
    u64 s25 = add2(x[2], x[5]), s34 = add2(x[3], x[4]);
    u64 d07 = fma2(x[7], p.M1, x[0]), d16 = fma2(x[6], p.M1, x[1]);
    u64 d25 = fma2(x[5], p.M1, x[2]), d34 = fma2(x[4], p.M1, x[3]);
    u64 e0 = add2(s07, s34), e1 = add2(s16, s25);
    u64 e2 = fma2(s34, p.M1, s07), e3 = fma2(s25, p.M1, s16);
    o[0] = mul2(p.G, add2(e0, e1));
    o[4] = mul2(p.G, fma2(e1, p.M1, e0));
    o[2] = fma2(e3, p.F, mul2(e2, p.E));
    o[6] = fma2(mul2(e3, p.E), p.M1, mul2(e2, p.F));
    o[1] = fma2(d34, p.D, fma2(d25, p.C, fma2(d16, p.B, mul2(d07, p.A))));
    o[3] = fma2(fma2(d34, p.C, fma2(d25, p.A, mul2(d16, p.D))), p.M1,
                mul2(d07, p.B));
    o[5] = fma2(mul2(d16, p.A), p.M1,
                fma2(d34, p.B, fma2(d25, p.D, mul2(d07, p.C))));
    o[7] = fma2(fma2(d34, p.A, mul2(d16, p.C)), p.M1,
                fma2(d25, p.B, mul2(d07, p.D)));
}

__device__ __forceinline__ void idct8p(const u64 x[8], u64 o[8], const PK& p) {
    u64 ee0 = mul2(p.G, add2(x[0], x[4]));
    u64 ee1 = mul2(p.G, fma2(x[4], p.M1, x[0]));
    u64 eo0 = fma2(x[6], p.F, mul2(x[2], p.E));
    u64 eo1 = fma2(mul2(x[6], p.E), p.M1, mul2(x[2], p.F));
    u64 ev0 = add2(ee0, eo0), ev1 = add2(ee1, eo1);
    u64 ev2 = fma2(eo1, p.M1, ee1), ev3 = fma2(eo0, p.M1, ee0);
    u64 od0 = fma2(x[7], p.D, fma2(x[5], p.C, fma2(x[3], p.B, mul2(x[1], p.A))));
    u64 od1 = fma2(fma2(x[7], p.C, fma2(x[5], p.A, mul2(x[3], p.D))), p.M1,
                   mul2(x[1], p.B));
    u64 od2 = fma2(mul2(x[3], p.A), p.M1,
                   fma2(x[7], p.B, fma2(x[5], p.D, mul2(x[1], p.C))));
    u64 od3 = fma2(fma2(x[7], p.A, mul2(x[3], p.C)), p.M1,
                   fma2(x[5], p.B, mul2(x[1], p.D)));
    o[0] = add2(ev0, od0); o[1] = add2(ev1, od1);
    o[2] = add2(ev2, od2); o[3] = add2(ev3, od3);
    o[4] = fma2(od3, p.M1, ev3); o[5] = fma2(od2, p.M1, ev2);
    o[6] = fma2(od1, p.M1, ev1); o[7] = fma2(od0, p.M1, ev0);
}

// ---------------- scalar DCTs (chroma path) -------------------------------
__device__ __forceinline__ float rne(float v) {
    float t = fmaf(v, 1.0f, MAGIC);
    return fmaf(t, 1.0f, -MAGIC);
}

__device__ __forceinline__ void fdct8(const float x[8], float o[8]) {
    float s07 = x[0] + x[7], s16 = x[1] + x[6], s25 = x[2] + x[5], s34 = x[3] + x[4];
    float d07 = x[0] - x[7], d16 = x[1] - x[6], d25 = x[2] - x[5], d34 = x[3] - x[4];
    float e0 = s07 + s34, e1 = s16 + s25, e2 = s07 - s34, e3 = s16 - s25;
    o[0] = G_ * (e0 + e1);
    o[4] = G_ * (e0 - e1);
    o[2] = fmaf( F_, e3, E_ * e2);
    o[6] = fmaf(-E_, e3, F_ * e2);
    o[1] = fmaf( D_, d34, fmaf( C_, d25, fmaf( B_, d16, A_ * d07)));
    o[3] = fmaf(-C_, d34, fmaf(-A_, d25, fmaf(-D_, d16, B_ * d07)));
    o[5] = fmaf( B_, d34, fmaf( D_, d25, fmaf(-A_, d16, C_ * d07)));
    o[7] = fmaf(-A_, d34, fmaf( B_, d25, fmaf(-C_, d16, D_ * d07)));
}

__device__ __forceinline__ void idct8(const float x[8], float o[8]) {
    float ee0 = G_ * (x[0] + x[4]);
    float ee1 = G_ * (x[0] - x[4]);
    float eo0 = fmaf( F_, x[6], E_ * x[2]);
    float eo1 = fmaf(-E_, x[6], F_ * x[2]);
    float ev0 = ee0 + eo0, ev1 = ee1 + eo1, ev2 = ee1 - eo1, ev3 = ee0 - eo0;
    float od0 = fmaf( D_, x[7], fmaf( C_, x[5], fmaf( B_, x[3], A_ * x[1])));
    float od1 = fmaf(-C_, x[7], fmaf(-A_, x[5], fmaf(-D_, x[3], B_ * x[1])));
    float od2 = fmaf( B_, x[7], fmaf( D_, x[5], fmaf(-A_, x[3], C_ * x[1])));
    float od3 = fmaf(-A_, x[7], fmaf( B_, x[5], fmaf(-C_, x[3], D_ * x[1])));
    o[0] = ev0 + od0; o[1] = ev1 + od1; o[2] = ev2 + od2; o[3] = ev3 + od3;
    o[4] = ev3 - od3; o[5] = ev2 - od2; o[6] = ev1 - od1; o[7] = ev0 - od0;
}

// Eklundh transpose: packed luma pair (u64 shfl = 2 SHFL) + scalar chroma.
__device__ __forceinline__ void transpose8p(u64 v01[8], float v2[8], int k) {
#pragma unroll
    for (int s = 1; s < 8; s <<= 1) {
        const bool up = (k & s) != 0;
#pragma unroll
        for (int j = 0; j < 8; j++) {
            if ((j & s) == 0) {
                const int jp = j | s;
                u64   sA = up ? v01[j] : v01[jp];
                float sB = up ? v2[j]  : v2[jp];
                u64   rA = __shfl_xor_sync(0xFFFFFFFFu, sA, s, 32);
                float rB = __shfl_xor_sync(0xFFFFFFFFu, sB, s, 32);
                if (up) { v01[j] = rA;  v2[j] = rB; }
                else    { v01[jp] = rA; v2[jp] = rB; }
            }
        }
    }
}

template <int S>
__device__ __forceinline__ void storerow(float* blk, int k, const float a[8]) {
    *reinterpret_cast<float4*>(blk + k * S)     = make_float4(a[0], a[1], a[2], a[3]);
    *reinterpret_cast<float4*>(blk + k * S + 4) = make_float4(a[4], a[5], a[6], a[7]);
}
template <int S>
__device__ __forceinline__ void loadrow(const float* blk, int k, float a[8]) {
    float4 v0 = *reinterpret_cast<const float4*>(blk + k * S);
    float4 v1 = *reinterpret_cast<const float4*>(blk + k * S + 4);
    a[0] = v0.x; a[1] = v0.y; a[2] = v0.z; a[3] = v0.w;
    a[4] = v1.x; a[5] = v1.y; a[6] = v1.z; a[7] = v1.w;
}

// Two luma blocks packed into f32x2 lanes + one scalar chroma block.
template <int SL, int SC>
__device__ __forceinline__ void jpeg_block3(float* b0, float* b1, float* b2, int k,
                                            const float2* __restrict__ tabL,
                                            const float2* __restrict__ tabC) {
    const PK p = mkpk();
    float x0[8], x1[8], x2[8], a2[8];
    u64 x01[8], a01[8];
    loadrow<SL>(b0, k, x0);
    loadrow<SL>(b1, k, x1);
    loadrow<SC>(b2, k, x2);
#pragma unroll
    for (int l = 0; l < 8; l++) x01[l] = pk2(x0[l], x1[l]);
    fdct8p(x01, a01, p);
    fdct8(x2, a2);
    transpose8p(a01, a2, k);
    fdct8p(a01, x01, p);
    fdct8(a2, x2);
#pragma unroll
    for (int l = 0; l < 8; l++) {
        float2 t = tabL[l * 8 + k];
        u64 iq2 = bc2(t.y), q2 = bc2(t.x);
        u64 v = fma2(x01[l], iq2, p.MG);   // rne fold: round(x*iq) via magic
        v = fma2(p.MG, p.M1, v);
        x01[l] = mul2(v, q2);
        float2 u = tabC[l * 8 + k];
        x2[l] = rne(x2[l] * u.y) * u.x;
    }
    idct8p(x01, a01, p);
    idct8(x2, a2);
    transpose8p(a01, a2, k);
    idct8p(a01, x01, p);
    idct8(a2, x2);
#pragma unroll
    for (int l = 0; l < 8; l++) upk2(x01[l], x0[l], x1[l]);
    storerow<SL>(b0, k, x0);
    storerow<SL>(b1, k, x1);
    storerow<SC>(b2, k, x2);
}

__global__ void __launch_bounds__(NTHR, 6)
jpeg_kernel(const float* __restrict__ in, float* __restrict__ out) {
    __shared__ float sY[TH * SYS];
    __shared__ float sCb[16 * SCS];
    __shared__ float sCr[16 * SCS];
    __shared__ float2 sTab[128];

    const int tid = threadIdx.x;
    const int tx0 = blockIdx.x * TW;
    const int ty0 = blockIdx.y * TH;
    const int img = blockIdx.z;

    sTab[tid] = c_tab2[tid];

    const float* src = in  + (((size_t)img * IMGW + ty0) * IMGW + tx0) * 3;
    float*       dst = out + (((size_t)img * IMGW + ty0) * IMGW + tx0) * 3;

    // ---------- phase 1: LDG.128 (6 loads up front), RGB->YCbCr, 4:2:0 -------
#pragma unroll
    for (int it = 0; it < 2; it++) {
        int sid = tid + it * NTHR;
        int col = sid & 15, rp = sid >> 4;
        const float* p = src + (rp * 2) * (IMGW * 3) + col * 12;
        const float* pr0 = p;
        const float* pr1 = p + (IMGW * 3);

        float4 qa0 = *reinterpret_cast<const float4*>(pr0);
        float4 qa1 = *reinterpret_cast<const float4*>(pr0 + 4);
        float4 qa2 = *reinterpret_cast<const float4*>(pr0 + 8);
        float4 qb0 = *reinterpret_cast<const float4*>(pr1);
        float4 qb1 = *reinterpret_cast<const float4*>(pr1 + 4);
        float4 qb2 = *reinterpret_cast<const float4*>(pr1 + 8);

        float cbs[2] = {0.0f, 0.0f}, crs[2] = {0.0f, 0.0f};
#pragma unroll
        for (int dy = 0; dy < 2; dy++) {
            float4 q0 = dy ? qb0 : qa0;
            float4 q1 = dy ? qb1 : qa1;
            float4 q2 = dy ? qb2 : qa2;
            float rv[4] = { q0.x, q0.w, q1.z, q2.y };
            float gv[4] = { q0.y, q1.x, q1.w, q2.z };
            float bv[4] = { q0.z, q1.y, q2.x, q2.w };
            float y4[4];
#pragma unroll
            for (int i = 0; i < 4; i++) {
                float r = floorf(rv[i] * 255.0f);
                float g = floorf(gv[i] * 255.0f);
                float b = floorf(bv[i] * 255.0f);
                y4[i] = fmaf(r, 0.299f, fmaf(g, 0.587f, fmaf(b, 0.114f, -128.0f)));
                cbs[i >> 1] += fmaf(r, -0.168736f, fmaf(g, -0.331264f, b * 0.5f));
                crs[i >> 1] += fmaf(r, 0.5f, fmaf(g, -0.418688f, b * (-0.081312f)));
            }
            *reinterpret_cast<float4*>(&sY[(rp * 2 + dy) * SYS + col * 4]) =
                make_float4(y4[0], y4[1], y4[2], y4[3]);
        }
        *reinterpret_cast<float2*>(&sCb[rp * SCS + col * 2]) =
            make_float2(cbs[0] * 0.25f, cbs[1] * 0.25f);
        *reinterpret_cast<float2*>(&sCr[rp * SCS + col * 2]) =
            make_float2(crs[0] * 0.25f, crs[1] * 0.25f);
    }
    __syncthreads();

    // ---------- phase 2: 16 groups x (packed luma pair + scalar chroma) ------
    {
        const int grp = tid >> 3;
        const int k   = tid & 7;

        const float2* tl = sTab;
        const float2* tc2 = sTab + 64;

        float* yb0 = sY + (grp >> 3) * (8 * SYS) + (grp & 7) * 8;
        float* yb1 = sY + ((grp >> 3) + 2) * (8 * SYS) + (grp & 7) * 8;

        int cg = grp & 7;
        float* cbase = (grp < 8) ? sCb : sCr;
        float* cb = cbase + (cg >> 2) * (8 * SCS) + (cg & 3) * 8;

        jpeg_block3<SYS, SCS>(yb0, yb1, cb, k, tl, tc2);
    }
    __syncthreads();

    // ---------- phase 3: upsample chroma, YCbCr->RGB, clip, round, STG.128 ---
#pragma unroll
    for (int it = 0; it < 2; it++) {
        int sid = tid + it * NTHR;
        int col = sid & 15, rp = sid >> 4;
        float2 cb2 = *reinterpret_cast<const float2*>(&sCb[rp * SCS + col * 2]);
        float2 cr2 = *reinterpret_cast<const float2*>(&sCr[rp * SCS + col * 2]);
        float cbv[4] = { cb2.x, cb2.x, cb2.y, cb2.y };
        float crv[4] = { cr2.x, cr2.x, cr2.y, cr2.y };
        float* p = dst + (rp * 2) * (IMGW * 3) + col * 12;
#pragma unroll
        for (int dy = 0; dy < 2; dy++) {
            float4 y4 = *reinterpret_cast<const float4*>(&sY[(rp * 2 + dy) * SYS + col * 4]);
            float yv[4] = { y4.x, y4.y, y4.z, y4.w };
            float o[12];
#pragma unroll
            for (int i = 0; i < 4; i++) {
                float y128 = yv[i] + 128.0f;
                float r2 = fmaf(crv[i], 1.402f, y128);
                float g2 = fmaf(cbv[i], -0.344136f, fmaf(crv[i], -0.714136f, y128));
                float b2 = fmaf(cbv[i], 1.772f, y128);
                o[i*3+0] = rne(fminf(fmaxf(r2, 0.0f), 255.0f)) * (1.0f / 255.0f);
                o[i*3+1] = rne(fminf(fmaxf(g2, 0.0f), 255.0f)) * (1.0f / 255.0f);
                o[i*3+2] = rne(fminf(fmaxf(b2, 0.0f), 255.0f)) * (1.0f / 255.0f);
            }
            float* pr = p + dy * (IMGW * 3);
            *reinterpret_cast<float4*>(pr)     = make_float4(o[0], o[1], o[2], o[3]);
            *reinterpret_cast<float4*>(pr + 4) = make_float4(o[4], o[5], o[6], o[7]);
            *reinterpret_cast<float4*>(pr + 8) = make_float4(o[8], o[9], o[10], o[11]);
        }
    }
}

extern "C" void kernel_launch(void* const* d_in, const int* in_sizes, int n_in,
                              void* d_out, int out_size) {
    (void)in_sizes; (void)n_in; (void)out_size;
    dim3 grid(IMGW / TW, IMGW / TH, 32);
    jpeg_kernel<<<grid, NTHR>>>((const float*)d_in[0], (float*)d_out);
}